// round 15
// baseline (speedup 1.0000x reference)
#include <cuda_runtime.h>
#include <math.h>

#define BB 8
#define CC 256
#define NN 4096
#define LL 8
#define HH 8
#define HDIM 32
#define FFD 768
#define BNT (BB*NN)

#if __CUDA_ARCH__ >= 900
#define GDC_WAIT() asm volatile("griddepcontrol.wait;" ::: "memory")
#else
#define GDC_WAIT()
#endif

__device__ float g_h[BB*NN*CC];
__device__ float g_u[BB*NN*CC];
__device__ float g_q[BB*NN*CC];
__device__ float g_kk[BB*NN*CC];
__device__ float g_v[BB*NN*CC];
__device__ float g_o[BB*NN*CC];
__device__ float g_g[BB*NN*FFD];   // FF scratch; also encoder proj [8][512][4096]
__device__ float g_pe[CC*NN];      // [256][4096]
__device__ float g_te[BB*CC];      // [8][256]
__device__ int   g_codes[BB*HH*NN];
__device__ int   g_order[BB*HH*NN];

// ---- SGEMM 128x64 tile, 8x4 microtile, 256 thr (R8/R12-proven) --------------------
// MODE 0: C=AB+bias  MODE 1: C=AB+bias+Res
template<int MODE>
__launch_bounds__(256)
__global__ void gemm_k(const float* __restrict__ A, int lda,
                       const float* __restrict__ B, int ldb,
                       float* __restrict__ C, int ldc,
                       const float* __restrict__ bias,
                       const float* __restrict__ Res, int K)
{
    __shared__ float As[16][128];
    __shared__ float Bs[16][64];
    const int tid = threadIdx.x;
    const int ty = tid >> 4, tx = tid & 15;
    const int ar = tid >> 1, ac = (tid & 1) * 8;
    const int br = tid >> 4, bc = (tid & 15) * 4;
    const float* Ap = A + (size_t)(blockIdx.y * 128 + ar) * lda + ac;
    const float* Bp = B + (size_t)br * ldb + blockIdx.x * 64 + bc;
    float acc[8][4];
    #pragma unroll
    for (int i = 0; i < 8; i++)
        #pragma unroll
        for (int j = 0; j < 4; j++) acc[i][j] = 0.f;

    float4 nb0 = *(const float4*)Bp;   // weight prefetch (independent)
    GDC_WAIT();

    for (int k0 = 0; k0 < K; k0 += 16) {
        float4 a0 = *(const float4*)(Ap + k0);
        float4 a1 = *(const float4*)(Ap + k0 + 4);
        float4 b0 = (k0 == 0) ? nb0 : *(const float4*)(Bp + (size_t)k0 * ldb);
        __syncthreads();
        As[ac + 0][ar] = a0.x; As[ac + 1][ar] = a0.y;
        As[ac + 2][ar] = a0.z; As[ac + 3][ar] = a0.w;
        As[ac + 4][ar] = a1.x; As[ac + 5][ar] = a1.y;
        As[ac + 6][ar] = a1.z; As[ac + 7][ar] = a1.w;
        *(float4*)&Bs[br][bc] = b0;
        __syncthreads();
        #pragma unroll
        for (int k = 0; k < 16; k++) {
            float4 fa0 = *(const float4*)&As[k][ty * 8];
            float4 fa1 = *(const float4*)&As[k][ty * 8 + 4];
            float4 fb  = *(const float4*)&Bs[k][tx * 4];
            float av[8] = {fa0.x, fa0.y, fa0.z, fa0.w, fa1.x, fa1.y, fa1.z, fa1.w};
            float bv[4] = {fb.x, fb.y, fb.z, fb.w};
            #pragma unroll
            for (int i = 0; i < 8; i++)
                #pragma unroll
                for (int j = 0; j < 4; j++)
                    acc[i][j] = fmaf(av[i], bv[j], acc[i][j]);
        }
    }
    const int row = blockIdx.y * 128 + ty * 8;
    const int col = blockIdx.x * 64 + tx * 4;
    float4 bi = make_float4(0.f, 0.f, 0.f, 0.f);
    if (bias) bi = *(const float4*)(bias + col);
    #pragma unroll
    for (int i = 0; i < 8; i++) {
        float4 v;
        v.x = __fadd_rn(acc[i][0], bi.x); v.y = __fadd_rn(acc[i][1], bi.y);
        v.z = __fadd_rn(acc[i][2], bi.z); v.w = __fadd_rn(acc[i][3], bi.w);
        float* cp = C + (size_t)(row + i) * ldc + col;
        if (MODE == 1) {
            float4 r = *(const float4*)(Res + (size_t)(row + i) * ldc + col);
            v.x = __fadd_rn(v.x, r.x); v.y = __fadd_rn(v.y, r.y);
            v.z = __fadd_rn(v.z, r.z); v.w = __fadd_rn(v.w, r.w);
        }
        *(float4*)cp = v;
    }
}

// ---- merged Q/V GEMM: blockIdx.z selects (W, b, C) --------------------------------
__launch_bounds__(256)
__global__ void gemm_qv(const float* __restrict__ A,
                        const float* __restrict__ W0, const float* __restrict__ W1,
                        const float* __restrict__ b0, const float* __restrict__ b1,
                        float* __restrict__ C0, float* __restrict__ C1)
{
    const int z = blockIdx.z;
    const float* B    = (z == 0) ? W0 : W1;
    const float* bias = (z == 0) ? b0 : b1;
    float* C          = (z == 0) ? C0 : C1;

    __shared__ float As[16][128];
    __shared__ float Bs[16][64];
    const int tid = threadIdx.x;
    const int ty = tid >> 4, tx = tid & 15;
    const int ar = tid >> 1, ac = (tid & 1) * 8;
    const int br = tid >> 4, bc = (tid & 15) * 4;
    const float* Ap = A + (size_t)(blockIdx.y * 128 + ar) * CC + ac;
    const float* Bp = B + (size_t)br * CC + blockIdx.x * 64 + bc;
    float acc[8][4];
    #pragma unroll
    for (int i = 0; i < 8; i++)
        #pragma unroll
        for (int j = 0; j < 4; j++) acc[i][j] = 0.f;

    float4 nb0 = *(const float4*)Bp;   // weight prefetch (independent)
    GDC_WAIT();

    #pragma unroll 1
    for (int k0 = 0; k0 < CC; k0 += 16) {
        float4 a0 = *(const float4*)(Ap + k0);
        float4 a1 = *(const float4*)(Ap + k0 + 4);
        float4 b0v = (k0 == 0) ? nb0 : *(const float4*)(Bp + (size_t)k0 * CC);
        __syncthreads();
        As[ac + 0][ar] = a0.x; As[ac + 1][ar] = a0.y;
        As[ac + 2][ar] = a0.z; As[ac + 3][ar] = a0.w;
        As[ac + 4][ar] = a1.x; As[ac + 5][ar] = a1.y;
        As[ac + 6][ar] = a1.z; As[ac + 7][ar] = a1.w;
        *(float4*)&Bs[br][bc] = b0v;
        __syncthreads();
        #pragma unroll
        for (int k = 0; k < 16; k++) {
            float4 fa0 = *(const float4*)&As[k][ty * 8];
            float4 fa1 = *(const float4*)&As[k][ty * 8 + 4];
            float4 fb  = *(const float4*)&Bs[k][tx * 4];
            float av[8] = {fa0.x, fa0.y, fa0.z, fa0.w, fa1.x, fa1.y, fa1.z, fa1.w};
            float bv[4] = {fb.x, fb.y, fb.z, fb.w};
            #pragma unroll
            for (int i = 0; i < 8; i++)
                #pragma unroll
                for (int j = 0; j < 4; j++)
                    acc[i][j] = fmaf(av[i], bv[j], acc[i][j]);
        }
    }
    const int row = blockIdx.y * 128 + ty * 8;
    const int col = blockIdx.x * 64 + tx * 4;
    float4 bi = *(const float4*)(bias + col);
    #pragma unroll
    for (int i = 0; i < 8; i++) {
        float4 v;
        v.x = __fadd_rn(acc[i][0], bi.x); v.y = __fadd_rn(acc[i][1], bi.y);
        v.z = __fadd_rn(acc[i][2], bi.z); v.w = __fadd_rn(acc[i][3], bi.w);
        *(float4*)(C + (size_t)(row + i) * CC + col) = v;
    }
}

// ---- fused FF dual-GEMM (R8/R12-proven): g = (A@Wa+ba) * relu(A@Wb+bb) -----------
__launch_bounds__(256)
__global__ void gemm_ff(const float* __restrict__ A,
                        const float* __restrict__ Ba, const float* __restrict__ Bb,
                        float* __restrict__ C,
                        const float* __restrict__ ba, const float* __restrict__ bb)
{
    __shared__ float As[16][128];
    __shared__ float Bsa[16][64];
    __shared__ float Bsb[16][64];
    const int tid = threadIdx.x;
    const int ty = tid >> 4, tx = tid & 15;
    const int ar = tid >> 1, ac = (tid & 1) * 8;
    const int br = tid >> 4, bc = (tid & 15) * 4;
    const float* Ap  = A + (size_t)(blockIdx.y * 128 + ar) * CC + ac;
    const float* Bpa = Ba + (size_t)br * FFD + blockIdx.x * 64 + bc;
    const float* Bpb = Bb + (size_t)br * FFD + blockIdx.x * 64 + bc;
    float accA[8][4], accB[8][4];
    #pragma unroll
    for (int i = 0; i < 8; i++)
        #pragma unroll
        for (int j = 0; j < 4; j++) { accA[i][j] = 0.f; accB[i][j] = 0.f; }

    float4 np0 = *(const float4*)Bpa;  // weight prefetch (independent)
    float4 nq0 = *(const float4*)Bpb;
    GDC_WAIT();

    #pragma unroll 1
    for (int k0 = 0; k0 < CC; k0 += 16) {
        float4 a0 = *(const float4*)(Ap + k0);
        float4 a1 = *(const float4*)(Ap + k0 + 4);
        float4 p0 = (k0 == 0) ? np0 : *(const float4*)(Bpa + (size_t)k0 * FFD);
        float4 q0 = (k0 == 0) ? nq0 : *(const float4*)(Bpb + (size_t)k0 * FFD);
        __syncthreads();
        As[ac + 0][ar] = a0.x; As[ac + 1][ar] = a0.y;
        As[ac + 2][ar] = a0.z; As[ac + 3][ar] = a0.w;
        As[ac + 4][ar] = a1.x; As[ac + 5][ar] = a1.y;
        As[ac + 6][ar] = a1.z; As[ac + 7][ar] = a1.w;
        *(float4*)&Bsa[br][bc] = p0;
        *(float4*)&Bsb[br][bc] = q0;
        __syncthreads();
        #pragma unroll
        for (int k = 0; k < 16; k++) {
            float4 fa0 = *(const float4*)&As[k][ty * 8];
            float4 fa1 = *(const float4*)&As[k][ty * 8 + 4];
            float4 fp  = *(const float4*)&Bsa[k][tx * 4];
            float4 fq  = *(const float4*)&Bsb[k][tx * 4];
            float av[8] = {fa0.x, fa0.y, fa0.z, fa0.w, fa1.x, fa1.y, fa1.z, fa1.w};
            float pv[4] = {fp.x, fp.y, fp.z, fp.w};
            float qv[4] = {fq.x, fq.y, fq.z, fq.w};
            #pragma unroll
            for (int ii = 0; ii < 8; ii++)
                #pragma unroll
                for (int j = 0; j < 4; j++) {
                    accA[ii][j] = fmaf(av[ii], pv[j], accA[ii][j]);
                    accB[ii][j] = fmaf(av[ii], qv[j], accB[ii][j]);
                }
        }
    }
    const int row = blockIdx.y * 128 + ty * 8;
    const int col = blockIdx.x * 64 + tx * 4;
    float4 ba4 = *(const float4*)(ba + col);
    float4 bb4 = *(const float4*)(bb + col);
    float bav[4] = {ba4.x, ba4.y, ba4.z, ba4.w};
    float bbv[4] = {bb4.x, bb4.y, bb4.z, bb4.w};
    #pragma unroll
    for (int i = 0; i < 8; i++) {
        float o[4];
        #pragma unroll
        for (int j = 0; j < 4; j++) {
            float at = __fadd_rn(accA[i][j], bav[j]);
            float bt = __fadd_rn(accB[i][j], bbv[j]);
            o[j] = __fmul_rn(at, fmaxf(bt, 0.f));
        }
        *(float4*)(C + (size_t)(row + i) * FFD + col) = make_float4(o[0], o[1], o[2], o[3]);
    }
}

// ---- encoder GEMM: proj[b,o,p] = sum_{c<512} encW[o,c]*embs[b,c,p] + enc_b[o] ----
__launch_bounds__(256)
__global__ void gemm_enc(const float* __restrict__ A, float* __restrict__ C,
                         const float* __restrict__ bias)
{
    __shared__ float As[16][128];
    __shared__ float Bs[16][64];
    const int b = blockIdx.z;
    const int tid = threadIdx.x;
    const int ty = tid >> 4, tx = tid & 15;
    const int ar = tid >> 1, ac = (tid & 1) * 8;
    const int br = tid >> 4, bc = (tid & 15) * 4;
    const float* Ap = A + (size_t)(blockIdx.y * 128 + ar) * 512 + ac;
    float acc[8][4];
    #pragma unroll
    for (int i = 0; i < 8; i++)
        #pragma unroll
        for (int j = 0; j < 4; j++) acc[i][j] = 0.f;

    GDC_WAIT();
    for (int k0 = 0; k0 < 512; k0 += 16) {
        float4 a0 = *(const float4*)(Ap + k0);
        float4 a1 = *(const float4*)(Ap + k0 + 4);
        int kk = k0 + br;
        float4 b0;
        if (kk < 256) b0 = *(const float4*)(g_pe + (size_t)kk * NN + blockIdx.x * 64 + bc);
        else { float tv = g_te[b * 256 + (kk - 256)]; b0 = make_float4(tv, tv, tv, tv); }
        __syncthreads();
        As[ac + 0][ar] = a0.x; As[ac + 1][ar] = a0.y;
        As[ac + 2][ar] = a0.z; As[ac + 3][ar] = a0.w;
        As[ac + 4][ar] = a1.x; As[ac + 5][ar] = a1.y;
        As[ac + 6][ar] = a1.z; As[ac + 7][ar] = a1.w;
        *(float4*)&Bs[br][bc] = b0;
        __syncthreads();
        #pragma unroll
        for (int k = 0; k < 16; k++) {
            float4 fa0 = *(const float4*)&As[k][ty * 8];
            float4 fa1 = *(const float4*)&As[k][ty * 8 + 4];
            float4 fb  = *(const float4*)&Bs[k][tx * 4];
            float av[8] = {fa0.x, fa0.y, fa0.z, fa0.w, fa1.x, fa1.y, fa1.z, fa1.w};
            float bv[4] = {fb.x, fb.y, fb.z, fb.w};
            #pragma unroll
            for (int i = 0; i < 8; i++)
                #pragma unroll
                for (int j = 0; j < 4; j++)
                    acc[i][j] = fmaf(av[i], bv[j], acc[i][j]);
        }
    }
    const int row = blockIdx.y * 128 + ty * 8;
    const int col = blockIdx.x * 64 + tx * 4;
    #pragma unroll
    for (int i = 0; i < 8; i++) {
        float bb0 = bias[row + i];
        float4 v;
        v.x = __fadd_rn(acc[i][0], bb0); v.y = __fadd_rn(acc[i][1], bb0);
        v.z = __fadd_rn(acc[i][2], bb0); v.w = __fadd_rn(acc[i][3], bb0);
        *(float4*)(C + ((size_t)b * 512 + row + i) * NN + col) = v;
    }
}

// ---- LayerNorm: strictly sequential in-order reductions --------------------------
__launch_bounds__(256)
__global__ void ln_k(const float* __restrict__ x, float* __restrict__ y,
                     const float* __restrict__ s, const float* __restrict__ b)
{
    __shared__ float tile[32][257];
    __shared__ float sm[32], sd[32];
    const int t0 = blockIdx.x * 32;
    const int tid = threadIdx.x;
    GDC_WAIT();
    for (int i = tid; i < 32 * 256; i += 256) {
        int r = i >> 8, c = i & 255;
        tile[r][c] = x[(size_t)(t0 + r) * CC + c];
    }
    __syncthreads();
    if (tid < 32) {
        float sum = 0.f;
        for (int i = 0; i < 256; i++) sum = __fadd_rn(sum, tile[tid][i]);
        float mean = __fdiv_rn(sum, 256.f);
        float vs = 0.f;
        for (int i = 0; i < 256; i++) {
            float d = __fsub_rn(tile[tid][i], mean);
            vs = __fadd_rn(vs, __fmul_rn(d, d));
        }
        float var = __fdiv_rn(vs, 255.f);
        sm[tid] = mean;
        sd[tid] = sqrtf(__fadd_rn(var, 1e-6f));
    }
    __syncthreads();
    for (int i = tid; i < 32 * 256; i += 256) {
        int r = i >> 8, c = i & 255;
        float t2 = __fdiv_rn(__fsub_rn(tile[r][c], sm[r]), sd[r]);
        y[(size_t)(t0 + r) * CC + c] = __fadd_rn(__fmul_rn(t2, s[c]), b[c]);
    }
}

// ---- LSH hash (R cached in smem; hh uniform per block) ----------------------------
__global__ void hash_k(const float* __restrict__ Rl)
{
    __shared__ float Rs[1024];
    const int hb = ((blockIdx.x * 8) >> 12) & 7;     // uniform across block
    for (int i = threadIdx.x; i < 1024; i += 256) Rs[i] = Rl[hb * 1024 + i];
    __syncthreads();
    int w = blockIdx.x * 8 + (threadIdx.x >> 5);
    int lane = threadIdx.x & 31;
    int n  = w & (NN - 1);
    int b  = w >> 15;
    float kv = g_kk[((size_t)(b * NN + n)) * CC + hb * HDIM + lane];
    float acc = 0.f;
    #pragma unroll
    for (int d = 0; d < 32; d++)
        acc = fmaf(__shfl_sync(0xffffffffu, kv, d), Rs[d * 32 + lane], acc);
    float val = acc; int idx = lane;
    float nacc = -acc;
    if (nacc > acc) { val = nacc; idx = lane + 32; }
    #pragma unroll
    for (int o = 16; o; o >>= 1) {
        float ov = __shfl_xor_sync(0xffffffffu, val, o);
        int   oi = __shfl_xor_sync(0xffffffffu, idx, o);
        if (ov > val || (ov == val && oi < idx)) { val = ov; idx = oi; }
    }
    if (lane == 0) g_codes[w] = idx;
}

// ---- stable counting sort per (b,h) ----------------------------------------------
__global__ void sort_k()
{
    const int bh = blockIdx.x;
    const int t = threadIdx.x;
    const int* cp = g_codes + (size_t)bh * NN;
    int* op = g_order + (size_t)bh * NN;
    __shared__ int lh[64 * 65];
    __shared__ int bstart[64];
    __shared__ int tot[64];
    for (int i = 0; i < 64; i++) lh[t * 65 + i] = 0;
    const int base = t * 64;
    for (int i = 0; i < 64; i++) { int c = cp[base + i]; lh[t * 65 + c]++; }
    __syncthreads();
    int run = 0;
    for (int r = 0; r < 64; r++) { int x = lh[r * 65 + t]; lh[r * 65 + t] = run; run += x; }
    tot[t] = run;
    __syncthreads();
    if (t == 0) { int s = 0; for (int i = 0; i < 64; i++) { bstart[i] = s; s += tot[i]; } }
    __syncthreads();
    int cnt[64];
    for (int i = 0; i < 64; i++) cnt[i] = 0;
    for (int i = 0; i < 64; i++) {
        int c = cp[base + i];
        int pos = bstart[c] + lh[t * 65 + c] + cnt[c]++;
        op[pos] = base + i;
    }
}

// ---- chunk attention: expf, sequential sum, normalize-then-AV ---------------------
__launch_bounds__(256)
__global__ void attn_k()
{
    const int m = blockIdx.x, hh = blockIdx.y, b = blockIdx.z;
    __shared__ float qs[64][33], ks[64][33], vs[64][33];
    __shared__ float P[64][65];
    __shared__ float rsum[64];
    __shared__ int sidx[64];
    const int tid = threadIdx.x;
    if (tid < 64) sidx[tid] = g_order[((size_t)(b * HH + hh)) * NN + m * 64 + tid];
    __syncthreads();
    const int row = tid >> 2, g = tid & 3;
    {
        int n0 = sidx[row];
        size_t off = ((size_t)(b * NN + n0)) * CC + hh * HDIM + g * 8;
        #pragma unroll
        for (int j = 0; j < 8; j++) {
            qs[row][g * 8 + j] = g_q[off + j];
            ks[row][g * 8 + j] = g_kk[off + j];
            vs[row][g * 8 + j] = g_v[off + j];
        }
    }
    __syncthreads();
    const float SQHD = 5.656854249492381f;  // sqrtf(32)
    float sc[16];
    float mx = -INFINITY;
    #pragma unroll
    for (int jj = 0; jj < 16; jj++) {
        int colI = g * 16 + jj;
        float sacc = 0.f;
        #pragma unroll
        for (int d = 0; d < 32; d++) sacc = fmaf(qs[row][d], ks[colI][d], sacc);
        sacc = __fdiv_rn(sacc, SQHD);
        sc[jj] = sacc;
        mx = fmaxf(mx, sacc);
    }
    mx = fmaxf(mx, __shfl_xor_sync(0xffffffffu, mx, 1));
    mx = fmaxf(mx, __shfl_xor_sync(0xffffffffu, mx, 2));
    #pragma unroll
    for (int jj = 0; jj < 16; jj++)
        P[row][g * 16 + jj] = expf(__fsub_rn(sc[jj], mx));   // fp32 pipe (≤2 ulp)
    __syncthreads();
    if (tid < 64) {
        float ssum = 0.f;
        for (int i = 0; i < 64; i++) ssum = __fadd_rn(ssum, P[tid][i]);
        rsum[tid] = ssum;
    }
    __syncthreads();
    float pn[16];
    #pragma unroll
    for (int jj = 0; jj < 16; jj++)
        pn[jj] = __fdiv_rn(P[row][g * 16 + jj], rsum[row]);
    __syncthreads();
    #pragma unroll
    for (int jj = 0; jj < 16; jj++) P[row][g * 16 + jj] = pn[jj];
    __syncthreads();
    float acc[8] = {0.f, 0.f, 0.f, 0.f, 0.f, 0.f, 0.f, 0.f};
    const int dg = g * 8;
    #pragma unroll 4
    for (int kk = 0; kk < 64; kk++) {
        float p = P[row][kk];
        #pragma unroll
        for (int j = 0; j < 8; j++) acc[j] = fmaf(p, vs[kk][dg + j], acc[j]);
    }
    int n0 = sidx[row];
    float* op = g_o + ((size_t)(b * NN + n0)) * CC + hh * HDIM + dg;
    #pragma unroll
    for (int j = 0; j < 8; j++) op[j] = acc[j];
}

// ---- encodings: double-precision transcendentals (feed the hash path; keep CR) ----
__global__ void pe_k()
{
    int idx = blockIdx.x * 256 + threadIdx.x;
    int c = idx >> 12, p = idx & 4095;
    int yy = p >> 6, xx = p & 63;
    const float L = (float)log(10000.0);
    float cf, pos; int is_sin;
    if (c < 64)       { cf = (float)c;         pos = (float)yy; is_sin = 1; }
    else if (c < 128) { cf = (float)(c - 64);  pos = (float)yy; is_sin = 0; }
    else if (c < 192) { cf = (float)(c - 128); pos = (float)xx; is_sin = 1; }
    else              { cf = (float)(c - 192); pos = (float)xx; is_sin = 0; }
    float t3 = __fdiv_rn(__fmul_rn(-L, cf), 64.f);
    float f  = (float)exp((double)t3);
    float a  = __fmul_rn(pos, f);
    g_pe[idx] = is_sin ? (float)sin((double)a) : (float)cos((double)a);
}

__global__ void te_k(const float* __restrict__ t)
{
    int idx = blockIdx.x * 256 + threadIdx.x;
    int b = idx >> 8, c = idx & 255;
    const float L = (float)log(10000.0);
    float cf = (float)(c < 128 ? c : c - 128);
    float t3 = __fdiv_rn(__fmul_rn(-L, cf), 128.f);
    float f  = (float)exp((double)t3);
    float a  = __fmul_rn(t[b], f);
    g_te[idx] = (c < 128) ? (float)sin((double)a) : (float)cos((double)a);
}

// h[b,p,c] = x[b,c,p]*proj[b,c,p] + proj[b,c+256,p]
__global__ void encode_k(const float* __restrict__ x, const float* __restrict__ proj)
{
    const int b = blockIdx.z;
    const int p0 = blockIdx.x * 32, c0 = blockIdx.y * 32;
    __shared__ float sx[32][33], sm[32][33], sb[32][33];
    const int tx = threadIdx.x, ty = threadIdx.y;
    GDC_WAIT();
    #pragma unroll
    for (int i = 0; i < 4; i++) {
        int c = c0 + ty + 8 * i;
        int p = p0 + tx;
        sx[ty + 8 * i][tx] = x[((size_t)b * CC + c) * NN + p];
        sm[ty + 8 * i][tx] = proj[((size_t)b * 512 + c) * NN + p];
        sb[ty + 8 * i][tx] = proj[((size_t)b * 512 + c + 256) * NN + p];
    }
    __syncthreads();
    #pragma unroll
    for (int i = 0; i < 4; i++) {
        int p = p0 + ty + 8 * i;
        int c = c0 + tx;
        float prod = __fmul_rn(sx[tx][ty + 8 * i], sm[tx][ty + 8 * i]);
        g_h[((size_t)b * NN + p) * CC + c] = __fadd_rn(prod, sb[tx][ty + 8 * i]);
    }
}

__global__ void out_k(float* __restrict__ out)
{
    const int b = blockIdx.z;
    const int p0 = blockIdx.x * 32, c0 = blockIdx.y * 32;
    __shared__ float s[32][33];
    const int tx = threadIdx.x, ty = threadIdx.y;
    GDC_WAIT();
    #pragma unroll
    for (int i = 0; i < 4; i++)
        s[ty + 8 * i][tx] = g_h[((size_t)b * NN + p0 + ty + 8 * i) * CC + c0 + tx];
    __syncthreads();
    #pragma unroll
    for (int i = 0; i < 4; i++)
        out[((size_t)b * CC + c0 + ty + 8 * i) * NN + p0 + tx] = s[tx][ty + 8 * i];
}

// ---- PDL launch helper (stream-aware) ---------------------------------------------
template<typename F, typename... Args>
static inline void launch_pdl(cudaStream_t st, F f, dim3 grid, dim3 block, Args... args)
{
    cudaLaunchConfig_t cfg = {};
    cfg.gridDim = grid;
    cfg.blockDim = block;
    cfg.stream = st;
    cudaLaunchAttribute attr[1];
    attr[0].id = cudaLaunchAttributeProgrammaticStreamSerialization;
    attr[0].val.programmaticStreamSerializationAllowed = 1;
    cfg.attrs = attr;
    cfg.numAttrs = 1;
    if (cudaLaunchKernelEx(&cfg, f, args...) != cudaSuccess) {
        cfg.attrs = nullptr;
        cfg.numAttrs = 0;
        cudaLaunchKernelEx(&cfg, f, args...);
    }
}

extern "C" void kernel_launch(void* const* d_in, const int* in_sizes, int n_in,
                              void* d_out, int out_size)
{
    (void)in_sizes; (void)n_in; (void)out_size;
    const float* x    = (const float*)d_in[0];
    const float* tt   = (const float*)d_in[1];
    const float* encW = (const float*)d_in[3];
    const float* encB = (const float*)d_in[4];
    const float* ln1s = (const float*)d_in[5];
    const float* ln1b = (const float*)d_in[6];
    const float* Wq   = (const float*)d_in[7];
    const float* bq   = (const float*)d_in[8];
    const float* Wk   = (const float*)d_in[9];
    const float* bk   = (const float*)d_in[10];
    const float* Wv   = (const float*)d_in[11];
    const float* bv   = (const float*)d_in[12];
    const float* Wo   = (const float*)d_in[13];
    const float* bo   = (const float*)d_in[14];
    const float* R    = (const float*)d_in[15];
    const float* ln2s = (const float*)d_in[16];
    const float* ln2b = (const float*)d_in[17];
    const float* Wa   = (const float*)d_in[18];
    const float* ba   = (const float*)d_in[19];
    const float* Wb   = (const float*)d_in[20];
    const float* bb   = (const float*)d_in[21];
    const float* Wc   = (const float*)d_in[22];
    const float* bc   = (const float*)d_in[23];
    float* out = (float*)d_out;

    float *ph, *pu, *pq, *pk, *pv, *po, *pg;
    cudaGetSymbolAddress((void**)&ph, g_h);
    cudaGetSymbolAddress((void**)&pu, g_u);
    cudaGetSymbolAddress((void**)&pq, g_q);
    cudaGetSymbolAddress((void**)&pk, g_kk);
    cudaGetSymbolAddress((void**)&pv, g_v);
    cudaGetSymbolAddress((void**)&po, g_o);
    cudaGetSymbolAddress((void**)&pg, g_g);

    cudaStream_t s0 = 0;            // main (legacy capture) stream
    cudaStream_t s2 = 0;
    cudaEvent_t evK = nullptr, evS = nullptr;
    bool forked =
        (cudaStreamCreateWithFlags(&s2, cudaStreamNonBlocking) == cudaSuccess) &&
        (cudaEventCreateWithFlags(&evK, cudaEventDisableTiming) == cudaSuccess) &&
        (cudaEventCreateWithFlags(&evS, cudaEventDisableTiming) == cudaSuccess);

    pe_k<<<4096, 256>>>();
    te_k<<<8, 256>>>(tt);
    launch_pdl(s0, gemm_enc, dim3(64, 4, BB), dim3(256), encW, pg, encB);
    launch_pdl(s0, encode_k, dim3(128, 8, BB), dim3(32, 8), x, pg);

    for (int l = 0; l < LL; l++) {
        launch_pdl(s0, ln_k, dim3(BNT / 32), dim3(256), (const float*)ph, pu,
                   ln1s + l * CC, ln1b + l * CC);
        // K GEMM first (hash depends only on K)
        launch_pdl(s0, gemm_k<0>, dim3(4, 256), dim3(256), (const float*)pu, (int)CC,
                   Wk + (size_t)l * CC * CC, (int)CC, pk, (int)CC,
                   bk + l * CC, (const float*)nullptr, (int)CC);
        if (forked) {
            cudaEventRecord(evK, s0);
            cudaStreamWaitEvent(s2, evK, 0);
            hash_k<<<32768, 256, 0, s2>>>(R + (size_t)l * HH * HDIM * 32);
            sort_k<<<64, 64, 0, s2>>>();
            cudaEventRecord(evS, s2);
            // Q,V GEMMs run concurrently with hash/sort on the main stream
            launch_pdl(s0, gemm_qv, dim3(4, 256, 2), dim3(256), (const float*)pu,
                       Wq + (size_t)l * CC * CC, Wv + (size_t)l * CC * CC,
                       bq + l * CC, bv + l * CC, pq, pv);
            cudaStreamWaitEvent(s0, evS, 0);
        } else {
            hash_k<<<32768, 256>>>(R + (size_t)l * HH * HDIM * 32);
            sort_k<<<64, 64>>>();
            launch_pdl(s0, gemm_qv, dim3(4, 256, 2), dim3(256), (const float*)pu,
                       Wq + (size_t)l * CC * CC, Wv + (size_t)l * CC * CC,
                       bq + l * CC, bv + l * CC, pq, pv);
        }
        // attn: plain launch (needs both fork results; no PDL across the join)
        attn_k<<<dim3(64, HH, BB), 256>>>();
        launch_pdl(s0, gemm_k<1>, dim3(4, 256), dim3(256), (const float*)po, (int)CC,
                   Wo + (size_t)l * CC * CC, (int)CC, ph, (int)CC,
                   bo + l * CC, (const float*)ph, (int)CC);
        launch_pdl(s0, ln_k, dim3(BNT / 32), dim3(256), (const float*)ph, pu,
                   ln2s + l * CC, ln2b + l * CC);
        launch_pdl(s0, gemm_ff, dim3(12, 256), dim3(256), (const float*)pu,
                   Wa + (size_t)l * CC * FFD, Wb + (size_t)l * CC * FFD, pg,
                   ba + l * FFD, bb + l * FFD);
        launch_pdl(s0, gemm_k<1>, dim3(4, 256), dim3(256), (const float*)pg, (int)FFD,
                   Wc + (size_t)l * FFD * CC, (int)CC, ph, (int)CC,
                   bc + l * CC, (const float*)ph, (int)FFD);
    }

    launch_pdl(s0, out_k, dim3(128, 8, BB), dim3(32, 8), out);

    if (forked) {
        cudaEventDestroy(evK);
        cudaEventDestroy(evS);
        cudaStreamDestroy(s2);
    } else {
        if (evK) cudaEventDestroy(evK);
        if (evS) cudaEventDestroy(evS);
        if (s2) cudaStreamDestroy(s2);
    }
}

// round 16
// speedup vs baseline: 1.0027x; 1.0027x over previous
#include <cuda_runtime.h>
#include <math.h>

#define BB 8
#define CC 256
#define NN 4096
#define LL 8
#define HH 8
#define HDIM 32
#define FFD 768
#define BNT (BB*NN)

#if __CUDA_ARCH__ >= 900
#define GDC_WAIT() asm volatile("griddepcontrol.wait;" ::: "memory")
#else
#define GDC_WAIT()
#endif

__device__ float g_h[BB*NN*CC];
__device__ float g_u[BB*NN*CC];
__device__ float g_q[BB*NN*CC];
__device__ float g_kk[BB*NN*CC];
__device__ float g_v[BB*NN*CC];
__device__ float g_o[BB*NN*CC];
__device__ float g_g[BB*NN*FFD];   // FF scratch; also encoder proj [8][512][4096]
__device__ float g_pe[CC*NN];      // [256][4096]
__device__ float g_te[BB*CC];      // [8][256]
__device__ int   g_codes[BB*HH*NN];
__device__ int   g_order[BB*HH*NN];

// ---- SGEMM 128x64 tile, 8x4 microtile, 256 thr (proven optimum) -------------------
// MODE 0: C=AB+bias  MODE 1: C=AB+bias+Res
template<int MODE>
__launch_bounds__(256)
__global__ void gemm_k(const float* __restrict__ A, int lda,
                       const float* __restrict__ B, int ldb,
                       float* __restrict__ C, int ldc,
                       const float* __restrict__ bias,
                       const float* __restrict__ Res, int K)
{
    __shared__ float As[16][128];
    __shared__ float Bs[16][64];
    const int tid = threadIdx.x;
    const int ty = tid >> 4, tx = tid & 15;
    const int ar = tid >> 1, ac = (tid & 1) * 8;
    const int br = tid >> 4, bc = (tid & 15) * 4;
    const float* Ap = A + (size_t)(blockIdx.y * 128 + ar) * lda + ac;
    const float* Bp = B + (size_t)br * ldb + blockIdx.x * 64 + bc;
    float acc[8][4];
    #pragma unroll
    for (int i = 0; i < 8; i++)
        #pragma unroll
        for (int j = 0; j < 4; j++) acc[i][j] = 0.f;

    // prefetch first B tile (weights: independent of predecessor kernel)
    float4 nb0 = *(const float4*)Bp;
    GDC_WAIT();

    for (int k0 = 0; k0 < K; k0 += 16) {
        float4 a0 = *(const float4*)(Ap + k0);
        float4 a1 = *(const float4*)(Ap + k0 + 4);
        float4 b0 = (k0 == 0) ? nb0 : *(const float4*)(Bp + (size_t)k0 * ldb);
        __syncthreads();
        As[ac + 0][ar] = a0.x; As[ac + 1][ar] = a0.y;
        As[ac + 2][ar] = a0.z; As[ac + 3][ar] = a0.w;
        As[ac + 4][ar] = a1.x; As[ac + 5][ar] = a1.y;
        As[ac + 6][ar] = a1.z; As[ac + 7][ar] = a1.w;
        *(float4*)&Bs[br][bc] = b0;
        __syncthreads();
        #pragma unroll
        for (int k = 0; k < 16; k++) {
            float4 fa0 = *(const float4*)&As[k][ty * 8];
            float4 fa1 = *(const float4*)&As[k][ty * 8 + 4];
            float4 fb  = *(const float4*)&Bs[k][tx * 4];
            float av[8] = {fa0.x, fa0.y, fa0.z, fa0.w, fa1.x, fa1.y, fa1.z, fa1.w};
            float bv[4] = {fb.x, fb.y, fb.z, fb.w};
            #pragma unroll
            for (int i = 0; i < 8; i++)
                #pragma unroll
                for (int j = 0; j < 4; j++)
                    acc[i][j] = fmaf(av[i], bv[j], acc[i][j]);
        }
    }
    const int row = blockIdx.y * 128 + ty * 8;
    const int col = blockIdx.x * 64 + tx * 4;
    float4 bi = make_float4(0.f, 0.f, 0.f, 0.f);
    if (bias) bi = *(const float4*)(bias + col);
    #pragma unroll
    for (int i = 0; i < 8; i++) {
        float4 v;
        v.x = __fadd_rn(acc[i][0], bi.x); v.y = __fadd_rn(acc[i][1], bi.y);
        v.z = __fadd_rn(acc[i][2], bi.z); v.w = __fadd_rn(acc[i][3], bi.w);
        float* cp = C + (size_t)(row + i) * ldc + col;
        if (MODE == 1) {
            float4 r = *(const float4*)(Res + (size_t)(row + i) * ldc + col);
            v.x = __fadd_rn(v.x, r.x); v.y = __fadd_rn(v.y, r.y);
            v.z = __fadd_rn(v.z, r.z); v.w = __fadd_rn(v.w, r.w);
        }
        *(float4*)cp = v;
    }
}

// ---- merged QKV GEMM: blockIdx.z selects (W, b, C) --------------------------------
__launch_bounds__(256)
__global__ void gemm_qkv(const float* __restrict__ A,
                         const float* __restrict__ W0, const float* __restrict__ W1,
                         const float* __restrict__ W2,
                         const float* __restrict__ b0, const float* __restrict__ b1,
                         const float* __restrict__ b2,
                         float* __restrict__ C0, float* __restrict__ C1,
                         float* __restrict__ C2)
{
    const int z = blockIdx.z;
    const float* B    = (z == 0) ? W0 : (z == 1) ? W1 : W2;
    const float* bias = (z == 0) ? b0 : (z == 1) ? b1 : b2;
    float* C          = (z == 0) ? C0 : (z == 1) ? C1 : C2;

    __shared__ float As[16][128];
    __shared__ float Bs[16][64];
    const int tid = threadIdx.x;
    const int ty = tid >> 4, tx = tid & 15;
    const int ar = tid >> 1, ac = (tid & 1) * 8;
    const int br = tid >> 4, bc = (tid & 15) * 4;
    const float* Ap = A + (size_t)(blockIdx.y * 128 + ar) * CC + ac;
    const float* Bp = B + (size_t)br * CC + blockIdx.x * 64 + bc;
    float acc[8][4];
    #pragma unroll
    for (int i = 0; i < 8; i++)
        #pragma unroll
        for (int j = 0; j < 4; j++) acc[i][j] = 0.f;

    float4 nb0 = *(const float4*)Bp;   // weight prefetch (independent)
    GDC_WAIT();

    #pragma unroll 1
    for (int k0 = 0; k0 < CC; k0 += 16) {
        float4 a0 = *(const float4*)(Ap + k0);
        float4 a1 = *(const float4*)(Ap + k0 + 4);
        float4 b0v = (k0 == 0) ? nb0 : *(const float4*)(Bp + (size_t)k0 * CC);
        __syncthreads();
        As[ac + 0][ar] = a0.x; As[ac + 1][ar] = a0.y;
        As[ac + 2][ar] = a0.z; As[ac + 3][ar] = a0.w;
        As[ac + 4][ar] = a1.x; As[ac + 5][ar] = a1.y;
        As[ac + 6][ar] = a1.z; As[ac + 7][ar] = a1.w;
        *(float4*)&Bs[br][bc] = b0v;
        __syncthreads();
        #pragma unroll
        for (int k = 0; k < 16; k++) {
            float4 fa0 = *(const float4*)&As[k][ty * 8];
            float4 fa1 = *(const float4*)&As[k][ty * 8 + 4];
            float4 fb  = *(const float4*)&Bs[k][tx * 4];
            float av[8] = {fa0.x, fa0.y, fa0.z, fa0.w, fa1.x, fa1.y, fa1.z, fa1.w};
            float bv[4] = {fb.x, fb.y, fb.z, fb.w};
            #pragma unroll
            for (int i = 0; i < 8; i++)
                #pragma unroll
                for (int j = 0; j < 4; j++)
                    acc[i][j] = fmaf(av[i], bv[j], acc[i][j]);
        }
    }
    const int row = blockIdx.y * 128 + ty * 8;
    const int col = blockIdx.x * 64 + tx * 4;
    float4 bi = *(const float4*)(bias + col);
    #pragma unroll
    for (int i = 0; i < 8; i++) {
        float4 v;
        v.x = __fadd_rn(acc[i][0], bi.x); v.y = __fadd_rn(acc[i][1], bi.y);
        v.z = __fadd_rn(acc[i][2], bi.z); v.w = __fadd_rn(acc[i][3], bi.w);
        *(float4*)(C + (size_t)(row + i) * CC + col) = v;
    }
}

// ---- fused FF dual-GEMM: g = (A@Wa+ba) * relu(A@Wb+bb) ---------------------------
__launch_bounds__(256)
__global__ void gemm_ff(const float* __restrict__ A,
                        const float* __restrict__ Ba, const float* __restrict__ Bb,
                        float* __restrict__ C,
                        const float* __restrict__ ba, const float* __restrict__ bb)
{
    __shared__ float As[16][128];
    __shared__ float Bsa[16][64];
    __shared__ float Bsb[16][64];
    const int tid = threadIdx.x;
    const int ty = tid >> 4, tx = tid & 15;
    const int ar = tid >> 1, ac = (tid & 1) * 8;
    const int br = tid >> 4, bc = (tid & 15) * 4;
    const float* Ap  = A + (size_t)(blockIdx.y * 128 + ar) * CC + ac;
    const float* Bpa = Ba + (size_t)br * FFD + blockIdx.x * 64 + bc;
    const float* Bpb = Bb + (size_t)br * FFD + blockIdx.x * 64 + bc;
    float accA[8][4], accB[8][4];
    #pragma unroll
    for (int i = 0; i < 8; i++)
        #pragma unroll
        for (int j = 0; j < 4; j++) { accA[i][j] = 0.f; accB[i][j] = 0.f; }

    float4 np0 = *(const float4*)Bpa;  // weight prefetch (independent)
    float4 nq0 = *(const float4*)Bpb;
    GDC_WAIT();

    #pragma unroll 1
    for (int k0 = 0; k0 < CC; k0 += 16) {
        float4 a0 = *(const float4*)(Ap + k0);
        float4 a1 = *(const float4*)(Ap + k0 + 4);
        float4 p0 = (k0 == 0) ? np0 : *(const float4*)(Bpa + (size_t)k0 * FFD);
        float4 q0 = (k0 == 0) ? nq0 : *(const float4*)(Bpb + (size_t)k0 * FFD);
        __syncthreads();
        As[ac + 0][ar] = a0.x; As[ac + 1][ar] = a0.y;
        As[ac + 2][ar] = a0.z; As[ac + 3][ar] = a0.w;
        As[ac + 4][ar] = a1.x; As[ac + 5][ar] = a1.y;
        As[ac + 6][ar] = a1.z; As[ac + 7][ar] = a1.w;
        *(float4*)&Bsa[br][bc] = p0;
        *(float4*)&Bsb[br][bc] = q0;
        __syncthreads();
        #pragma unroll
        for (int k = 0; k < 16; k++) {
            float4 fa0 = *(const float4*)&As[k][ty * 8];
            float4 fa1 = *(const float4*)&As[k][ty * 8 + 4];
            float4 fp  = *(const float4*)&Bsa[k][tx * 4];
            float4 fq  = *(const float4*)&Bsb[k][tx * 4];
            float av[8] = {fa0.x, fa0.y, fa0.z, fa0.w, fa1.x, fa1.y, fa1.z, fa1.w};
            float pv[4] = {fp.x, fp.y, fp.z, fp.w};
            float qv[4] = {fq.x, fq.y, fq.z, fq.w};
            #pragma unroll
            for (int ii = 0; ii < 8; ii++)
                #pragma unroll
                for (int j = 0; j < 4; j++) {
                    accA[ii][j] = fmaf(av[ii], pv[j], accA[ii][j]);
                    accB[ii][j] = fmaf(av[ii], qv[j], accB[ii][j]);
                }
        }
    }
    const int row = blockIdx.y * 128 + ty * 8;
    const int col = blockIdx.x * 64 + tx * 4;
    float4 ba4 = *(const float4*)(ba + col);
    float4 bb4 = *(const float4*)(bb + col);
    float bav[4] = {ba4.x, ba4.y, ba4.z, ba4.w};
    float bbv[4] = {bb4.x, bb4.y, bb4.z, bb4.w};
    #pragma unroll
    for (int i = 0; i < 8; i++) {
        float o[4];
        #pragma unroll
        for (int j = 0; j < 4; j++) {
            float at = __fadd_rn(accA[i][j], bav[j]);
            float bt = __fadd_rn(accB[i][j], bbv[j]);
            o[j] = __fmul_rn(at, fmaxf(bt, 0.f));
        }
        *(float4*)(C + (size_t)(row + i) * FFD + col) = make_float4(o[0], o[1], o[2], o[3]);
    }
}

// ---- encoder GEMM: proj[b,o,p] = sum_{c<512} encW[o,c]*embs[b,c,p] + enc_b[o] ----
__launch_bounds__(256)
__global__ void gemm_enc(const float* __restrict__ A, float* __restrict__ C,
                         const float* __restrict__ bias)
{
    __shared__ float As[16][128];
    __shared__ float Bs[16][64];
    const int b = blockIdx.z;
    const int tid = threadIdx.x;
    const int ty = tid >> 4, tx = tid & 15;
    const int ar = tid >> 1, ac = (tid & 1) * 8;
    const int br = tid >> 4, bc = (tid & 15) * 4;
    const float* Ap = A + (size_t)(blockIdx.y * 128 + ar) * 512 + ac;
    float acc[8][4];
    #pragma unroll
    for (int i = 0; i < 8; i++)
        #pragma unroll
        for (int j = 0; j < 4; j++) acc[i][j] = 0.f;

    GDC_WAIT();
    for (int k0 = 0; k0 < 512; k0 += 16) {
        float4 a0 = *(const float4*)(Ap + k0);
        float4 a1 = *(const float4*)(Ap + k0 + 4);
        int kk = k0 + br;
        float4 b0;
        if (kk < 256) b0 = *(const float4*)(g_pe + (size_t)kk * NN + blockIdx.x * 64 + bc);
        else { float tv = g_te[b * 256 + (kk - 256)]; b0 = make_float4(tv, tv, tv, tv); }
        __syncthreads();
        As[ac + 0][ar] = a0.x; As[ac + 1][ar] = a0.y;
        As[ac + 2][ar] = a0.z; As[ac + 3][ar] = a0.w;
        As[ac + 4][ar] = a1.x; As[ac + 5][ar] = a1.y;
        As[ac + 6][ar] = a1.z; As[ac + 7][ar] = a1.w;
        *(float4*)&Bs[br][bc] = b0;
        __syncthreads();
        #pragma unroll
        for (int k = 0; k < 16; k++) {
            float4 fa0 = *(const float4*)&As[k][ty * 8];
            float4 fa1 = *(const float4*)&As[k][ty * 8 + 4];
            float4 fb  = *(const float4*)&Bs[k][tx * 4];
            float av[8] = {fa0.x, fa0.y, fa0.z, fa0.w, fa1.x, fa1.y, fa1.z, fa1.w};
            float bv[4] = {fb.x, fb.y, fb.z, fb.w};
            #pragma unroll
            for (int i = 0; i < 8; i++)
                #pragma unroll
                for (int j = 0; j < 4; j++)
                    acc[i][j] = fmaf(av[i], bv[j], acc[i][j]);
        }
    }
    const int row = blockIdx.y * 128 + ty * 8;
    const int col = blockIdx.x * 64 + tx * 4;
    #pragma unroll
    for (int i = 0; i < 8; i++) {
        float bb0 = bias[row + i];
        float4 v;
        v.x = __fadd_rn(acc[i][0], bb0); v.y = __fadd_rn(acc[i][1], bb0);
        v.z = __fadd_rn(acc[i][2], bb0); v.w = __fadd_rn(acc[i][3], bb0);
        *(float4*)(C + ((size_t)b * 512 + row + i) * NN + col) = v;
    }
}

// ---- LayerNorm: strictly sequential in-order reductions --------------------------
__launch_bounds__(256)
__global__ void ln_k(const float* __restrict__ x, float* __restrict__ y,
                     const float* __restrict__ s, const float* __restrict__ b)
{
    __shared__ float tile[32][257];
    __shared__ float sm[32], sd[32];
    const int t0 = blockIdx.x * 32;
    const int tid = threadIdx.x;
    GDC_WAIT();
    for (int i = tid; i < 32 * 256; i += 256) {
        int r = i >> 8, c = i & 255;
        tile[r][c] = x[(size_t)(t0 + r) * CC + c];
    }
    __syncthreads();
    if (tid < 32) {
        float sum = 0.f;
        for (int i = 0; i < 256; i++) sum = __fadd_rn(sum, tile[tid][i]);
        float mean = __fdiv_rn(sum, 256.f);
        float vs = 0.f;
        for (int i = 0; i < 256; i++) {
            float d = __fsub_rn(tile[tid][i], mean);
            vs = __fadd_rn(vs, __fmul_rn(d, d));
        }
        float var = __fdiv_rn(vs, 255.f);
        sm[tid] = mean;
        sd[tid] = sqrtf(__fadd_rn(var, 1e-6f));
    }
    __syncthreads();
    for (int i = tid; i < 32 * 256; i += 256) {
        int r = i >> 8, c = i & 255;
        float t2 = __fdiv_rn(__fsub_rn(tile[r][c], sm[r]), sd[r]);
        y[(size_t)(t0 + r) * CC + c] = __fadd_rn(__fmul_rn(t2, s[c]), b[c]);
    }
}

// ---- LSH hash (R cached in smem BEFORE wait; R is an input, independent) ----------
__global__ void hash_k(const float* __restrict__ Rl)
{
    __shared__ float Rs[1024];
    const int hb = ((blockIdx.x * 8) >> 12) & 7;     // uniform across block
    for (int i = threadIdx.x; i < 1024; i += 256) Rs[i] = Rl[hb * 1024 + i];
    __syncthreads();
    GDC_WAIT();
    int w = blockIdx.x * 8 + (threadIdx.x >> 5);
    int lane = threadIdx.x & 31;
    int n  = w & (NN - 1);
    int b  = w >> 15;
    float kv = g_kk[((size_t)(b * NN + n)) * CC + hb * HDIM + lane];
    float acc = 0.f;
    #pragma unroll
    for (int d = 0; d < 32; d++)
        acc = fmaf(__shfl_sync(0xffffffffu, kv, d), Rs[d * 32 + lane], acc);
    float val = acc; int idx = lane;
    float nacc = -acc;
    if (nacc > acc) { val = nacc; idx = lane + 32; }
    #pragma unroll
    for (int o = 16; o; o >>= 1) {
        float ov = __shfl_xor_sync(0xffffffffu, val, o);
        int   oi = __shfl_xor_sync(0xffffffffu, idx, o);
        if (ov > val || (ov == val && oi < idx)) { val = ov; idx = oi; }
    }
    if (lane == 0) g_codes[w] = idx;
}

// ---- stable counting sort per (b,h) ----------------------------------------------
__global__ void sort_k()
{
    const int bh = blockIdx.x;
    const int t = threadIdx.x;
    GDC_WAIT();
    const int* cp = g_codes + (size_t)bh * NN;
    int* op = g_order + (size_t)bh * NN;
    __shared__ int lh[64 * 65];
    __shared__ int bstart[64];
    __shared__ int tot[64];
    for (int i = 0; i < 64; i++) lh[t * 65 + i] = 0;
    const int base = t * 64;
    for (int i = 0; i < 64; i++) { int c = cp[base + i]; lh[t * 65 + c]++; }
    __syncthreads();
    int run = 0;
    for (int r = 0; r < 64; r++) { int x = lh[r * 65 + t]; lh[r * 65 + t] = run; run += x; }
    tot[t] = run;
    __syncthreads();
    if (t == 0) { int s = 0; for (int i = 0; i < 64; i++) { bstart[i] = s; s += tot[i]; } }
    __syncthreads();
    int cnt[64];
    for (int i = 0; i < 64; i++) cnt[i] = 0;
    for (int i = 0; i < 64; i++) {
        int c = cp[base + i];
        int pos = bstart[c] + lh[t * 65 + c] + cnt[c]++;
        op[pos] = base + i;
    }
}

// ---- chunk attention: expf, sequential sum, normalize-then-AV ---------------------
__launch_bounds__(256)
__global__ void attn_k()
{
    const int m = blockIdx.x, hh = blockIdx.y, b = blockIdx.z;
    __shared__ float qs[64][33], ks[64][33], vs[64][33];
    __shared__ float P[64][65];
    __shared__ float rsum[64];
    __shared__ int sidx[64];
    const int tid = threadIdx.x;
    GDC_WAIT();
    if (tid < 64) sidx[tid] = g_order[((size_t)(b * HH + hh)) * NN + m * 64 + tid];
    __syncthreads();
    const int row = tid >> 2, g = tid & 3;
    {
        int n0 = sidx[row];
        size_t off = ((size_t)(b * NN + n0)) * CC + hh * HDIM + g * 8;
        #pragma unroll
        for (int j = 0; j < 8; j++) {
            qs[row][g * 8 + j] = g_q[off + j];
            ks[row][g * 8 + j] = g_kk[off + j];
            vs[row][g * 8 + j] = g_v[off + j];
        }
    }
    __syncthreads();
    const float SQHD = 5.656854249492381f;  // sqrtf(32)
    float sc[16];
    float mx = -INFINITY;
    #pragma unroll
    for (int jj = 0; jj < 16; jj++) {
        int colI = g * 16 + jj;
        float sacc = 0.f;
        #pragma unroll
        for (int d = 0; d < 32; d++) sacc = fmaf(qs[row][d], ks[colI][d], sacc);
        sacc = __fdiv_rn(sacc, SQHD);
        sc[jj] = sacc;
        mx = fmaxf(mx, sacc);
    }
    mx = fmaxf(mx, __shfl_xor_sync(0xffffffffu, mx, 1));
    mx = fmaxf(mx, __shfl_xor_sync(0xffffffffu, mx, 2));
    #pragma unroll
    for (int jj = 0; jj < 16; jj++)
        P[row][g * 16 + jj] = expf(__fsub_rn(sc[jj], mx));   // fp32 pipe (≤2 ulp)
    __syncthreads();
    if (tid < 64) {
        float ssum = 0.f;
        for (int i = 0; i < 64; i++) ssum = __fadd_rn(ssum, P[tid][i]);
        rsum[tid] = ssum;
    }
    __syncthreads();
    float pn[16];
    #pragma unroll
    for (int jj = 0; jj < 16; jj++)
        pn[jj] = __fdiv_rn(P[row][g * 16 + jj], rsum[row]);
    __syncthreads();
    #pragma unroll
    for (int jj = 0; jj < 16; jj++) P[row][g * 16 + jj] = pn[jj];
    __syncthreads();
    float acc[8] = {0.f, 0.f, 0.f, 0.f, 0.f, 0.f, 0.f, 0.f};
    const int dg = g * 8;
    #pragma unroll 4
    for (int kk = 0; kk < 64; kk++) {
        float p = P[row][kk];
        #pragma unroll
        for (int j = 0; j < 8; j++) acc[j] = fmaf(p, vs[kk][dg + j], acc[j]);
    }
    int n0 = sidx[row];
    float* op = g_o + ((size_t)(b * NN + n0)) * CC + hh * HDIM + dg;
    #pragma unroll
    for (int j = 0; j < 8; j++) op[j] = acc[j];
}

// ---- encodings: double-precision transcendentals (feed the hash path; keep CR) ----
__global__ void pe_k()
{
    int idx = blockIdx.x * 256 + threadIdx.x;
    int c = idx >> 12, p = idx & 4095;
    int yy = p >> 6, xx = p & 63;
    const float L = (float)log(10000.0);
    float cf, pos; int is_sin;
    if (c < 64)       { cf = (float)c;         pos = (float)yy; is_sin = 1; }
    else if (c < 128) { cf = (float)(c - 64);  pos = (float)yy; is_sin = 0; }
    else if (c < 192) { cf = (float)(c - 128); pos = (float)xx; is_sin = 1; }
    else              { cf = (float)(c - 192); pos = (float)xx; is_sin = 0; }
    float t3 = __fdiv_rn(__fmul_rn(-L, cf), 64.f);
    float f  = (float)exp((double)t3);
    float a  = __fmul_rn(pos, f);
    g_pe[idx] = is_sin ? (float)sin((double)a) : (float)cos((double)a);
}

__global__ void te_k(const float* __restrict__ t)
{
    int idx = blockIdx.x * 256 + threadIdx.x;
    int b = idx >> 8, c = idx & 255;
    const float L = (float)log(10000.0);
    float cf = (float)(c < 128 ? c : c - 128);
    float t3 = __fdiv_rn(__fmul_rn(-L, cf), 128.f);
    float f  = (float)exp((double)t3);
    float a  = __fmul_rn(t[b], f);
    g_te[idx] = (c < 128) ? (float)sin((double)a) : (float)cos((double)a);
}

// h[b,p,c] = x[b,c,p]*proj[b,c,p] + proj[b,c+256,p]
__global__ void encode_k(const float* __restrict__ x, const float* __restrict__ proj)
{
    const int b = blockIdx.z;
    const int p0 = blockIdx.x * 32, c0 = blockIdx.y * 32;
    __shared__ float sx[32][33], sm[32][33], sb[32][33];
    const int tx = threadIdx.x, ty = threadIdx.y;
    GDC_WAIT();
    #pragma unroll
    for (int i = 0; i < 4; i++) {
        int c = c0 + ty + 8 * i;
        int p = p0 + tx;
        sx[ty + 8 * i][tx] = x[((size_t)b * CC + c) * NN + p];
        sm[ty + 8 * i][tx] = proj[((size_t)b * 512 + c) * NN + p];
        sb[ty + 8 * i][tx] = proj[((size_t)b * 512 + c + 256) * NN + p];
    }
    __syncthreads();
    #pragma unroll
    for (int i = 0; i < 4; i++) {
        int p = p0 + ty + 8 * i;
        int c = c0 + tx;
        float prod = __fmul_rn(sx[tx][ty + 8 * i], sm[tx][ty + 8 * i]);
        g_h[((size_t)b * NN + p) * CC + c] = __fadd_rn(prod, sb[tx][ty + 8 * i]);
    }
}

__global__ void out_k(float* __restrict__ out)
{
    const int b = blockIdx.z;
    const int p0 = blockIdx.x * 32, c0 = blockIdx.y * 32;
    __shared__ float s[32][33];
    const int tx = threadIdx.x, ty = threadIdx.y;
    GDC_WAIT();
    #pragma unroll
    for (int i = 0; i < 4; i++)
        s[ty + 8 * i][tx] = g_h[((size_t)b * NN + p0 + ty + 8 * i) * CC + c0 + tx];
    __syncthreads();
    #pragma unroll
    for (int i = 0; i < 4; i++)
        out[((size_t)b * CC + c0 + ty + 8 * i) * NN + p0 + tx] = s[tx][ty + 8 * i];
}

// ---- PDL launch helper ------------------------------------------------------------
template<typename F, typename... Args>
static inline void launch_pdl(F f, dim3 grid, dim3 block, Args... args)
{
    cudaLaunchConfig_t cfg = {};
    cfg.gridDim = grid;
    cfg.blockDim = block;
    cudaLaunchAttribute attr[1];
    attr[0].id = cudaLaunchAttributeProgrammaticStreamSerialization;
    attr[0].val.programmaticStreamSerializationAllowed = 1;
    cfg.attrs = attr;
    cfg.numAttrs = 1;
    if (cudaLaunchKernelEx(&cfg, f, args...) != cudaSuccess) {
        cfg.attrs = nullptr;
        cfg.numAttrs = 0;
        cudaLaunchKernelEx(&cfg, f, args...);
    }
}

extern "C" void kernel_launch(void* const* d_in, const int* in_sizes, int n_in,
                              void* d_out, int out_size)
{
    (void)in_sizes; (void)n_in; (void)out_size;
    const float* x    = (const float*)d_in[0];
    const float* tt   = (const float*)d_in[1];
    const float* encW = (const float*)d_in[3];
    const float* encB = (const float*)d_in[4];
    const float* ln1s = (const float*)d_in[5];
    const float* ln1b = (const float*)d_in[6];
    const float* Wq   = (const float*)d_in[7];
    const float* bq   = (const float*)d_in[8];
    const float* Wk   = (const float*)d_in[9];
    const float* bk   = (const float*)d_in[10];
    const float* Wv   = (const float*)d_in[11];
    const float* bv   = (const float*)d_in[12];
    const float* Wo   = (const float*)d_in[13];
    const float* bo   = (const float*)d_in[14];
    const float* R    = (const float*)d_in[15];
    const float* ln2s = (const float*)d_in[16];
    const float* ln2b = (const float*)d_in[17];
    const float* Wa   = (const float*)d_in[18];
    const float* ba   = (const float*)d_in[19];
    const float* Wb   = (const float*)d_in[20];
    const float* bb   = (const float*)d_in[21];
    const float* Wc   = (const float*)d_in[22];
    const float* bc   = (const float*)d_in[23];
    float* out = (float*)d_out;

    float *ph, *pu, *pq, *pk, *pv, *po, *pg;
    cudaGetSymbolAddress((void**)&ph, g_h);
    cudaGetSymbolAddress((void**)&pu, g_u);
    cudaGetSymbolAddress((void**)&pq, g_q);
    cudaGetSymbolAddress((void**)&pk, g_kk);
    cudaGetSymbolAddress((void**)&pv, g_v);
    cudaGetSymbolAddress((void**)&po, g_o);
    cudaGetSymbolAddress((void**)&pg, g_g);

    pe_k<<<4096, 256>>>();
    te_k<<<8, 256>>>(tt);
    launch_pdl(gemm_enc, dim3(64, 4, BB), dim3(256), encW, pg, encB);
    launch_pdl(encode_k, dim3(128, 8, BB), dim3(32, 8), x, pg);

    for (int l = 0; l < LL; l++) {
        launch_pdl(ln_k, dim3(BNT / 32), dim3(256), (const float*)ph, pu,
                   ln1s + l * CC, ln1b + l * CC);
        launch_pdl(gemm_qkv, dim3(4, 256, 3), dim3(256), (const float*)pu,
                   Wq + (size_t)l * CC * CC, Wk + (size_t)l * CC * CC, Wv + (size_t)l * CC * CC,
                   bq + l * CC, bk + l * CC, bv + l * CC, pq, pk, pv);
        launch_pdl(hash_k, dim3(32768), dim3(256), R + (size_t)l * HH * HDIM * 32);
        launch_pdl(sort_k, dim3(64), dim3(64));
        launch_pdl(attn_k, dim3(64, HH, BB), dim3(256));
        launch_pdl(gemm_k<1>, dim3(4, 256), dim3(256), (const float*)po, (int)CC,
                   Wo + (size_t)l * CC * CC, (int)CC, ph, (int)CC,
                   bo + l * CC, (const float*)ph, (int)CC);
        launch_pdl(ln_k, dim3(BNT / 32), dim3(256), (const float*)ph, pu,
                   ln2s + l * CC, ln2b + l * CC);
        launch_pdl(gemm_ff, dim3(12, 256), dim3(256), (const float*)pu,
                   Wa + (size_t)l * CC * FFD, Wb + (size_t)l * CC * FFD, pg,
                   ba + l * FFD, bb + l * FFD);
        launch_pdl(gemm_k<1>, dim3(4, 256), dim3(256), (const float*)pg, (int)FFD,
                   Wc + (size_t)l * FFD * CC, (int)CC, ph, (int)CC,
                   bc + l * CC, (const float*)ph, (int)FFD);
    }

    launch_pdl(out_k, dim3(128, 8, BB), dim3(32, 8), out);
}

// round 17
// speedup vs baseline: 1.0196x; 1.0169x over previous
#include <cuda_runtime.h>
#include <math.h>

#define BB 8
#define CC 256
#define NN 4096
#define LL 8
#define HH 8
#define HDIM 32
#define FFD 768
#define BNT (BB*NN)

#if __CUDA_ARCH__ >= 900
#define GDC_WAIT() asm volatile("griddepcontrol.wait;" ::: "memory")
#else
#define GDC_WAIT()
#endif

__device__ float g_h[BB*NN*CC];
__device__ float g_u[BB*NN*CC];   // layer scratch; also encoder partial S [512][4096]
__device__ float g_q[BB*NN*CC];
__device__ float g_kk[BB*NN*CC];
__device__ float g_v[BB*NN*CC];
__device__ float g_o[BB*NN*CC];
__device__ float g_g[BB*NN*FFD];  // FF scratch; also encoder proj [8][512][4096]
__device__ float g_pe[CC*NN];     // [256][4096]
__device__ float g_te[BB*CC];     // [8][256]
__device__ int   g_codes[BB*HH*NN];
__device__ int   g_order[BB*HH*NN];

// ---- SGEMM 128x64 tile, 8x4 microtile, 256 thr (proven optimum) -------------------
// MODE 0: C=AB+bias(or 0 if null)  MODE 1: C=AB+bias+Res
template<int MODE>
__launch_bounds__(256)
__global__ void gemm_k(const float* __restrict__ A, int lda,
                       const float* __restrict__ B, int ldb,
                       float* __restrict__ C, int ldc,
                       const float* __restrict__ bias,
                       const float* __restrict__ Res, int K)
{
    __shared__ float As[16][128];
    __shared__ float Bs[16][64];
    const int tid = threadIdx.x;
    const int ty = tid >> 4, tx = tid & 15;
    const int ar = tid >> 1, ac = (tid & 1) * 8;
    const int br = tid >> 4, bc = (tid & 15) * 4;
    const float* Ap = A + (size_t)(blockIdx.y * 128 + ar) * lda + ac;
    const float* Bp = B + (size_t)br * ldb + blockIdx.x * 64 + bc;
    float acc[8][4];
    #pragma unroll
    for (int i = 0; i < 8; i++)
        #pragma unroll
        for (int j = 0; j < 4; j++) acc[i][j] = 0.f;

    // prefetch first B tile (only valid pre-wait when B is a kernel input)
    float4 nb0 = *(const float4*)Bp;
    GDC_WAIT();

    for (int k0 = 0; k0 < K; k0 += 16) {
        float4 a0 = *(const float4*)(Ap + k0);
        float4 a1 = *(const float4*)(Ap + k0 + 4);
        float4 b0 = (k0 == 0) ? nb0 : *(const float4*)(Bp + (size_t)k0 * ldb);
        __syncthreads();
        As[ac + 0][ar] = a0.x; As[ac + 1][ar] = a0.y;
        As[ac + 2][ar] = a0.z; As[ac + 3][ar] = a0.w;
        As[ac + 4][ar] = a1.x; As[ac + 5][ar] = a1.y;
        As[ac + 6][ar] = a1.z; As[ac + 7][ar] = a1.w;
        *(float4*)&Bs[br][bc] = b0;
        __syncthreads();
        #pragma unroll
        for (int k = 0; k < 16; k++) {
            float4 fa0 = *(const float4*)&As[k][ty * 8];
            float4 fa1 = *(const float4*)&As[k][ty * 8 + 4];
            float4 fb  = *(const float4*)&Bs[k][tx * 4];
            float av[8] = {fa0.x, fa0.y, fa0.z, fa0.w, fa1.x, fa1.y, fa1.z, fa1.w};
            float bv[4] = {fb.x, fb.y, fb.z, fb.w};
            #pragma unroll
            for (int i = 0; i < 8; i++)
                #pragma unroll
                for (int j = 0; j < 4; j++)
                    acc[i][j] = fmaf(av[i], bv[j], acc[i][j]);
        }
    }
    const int row = blockIdx.y * 128 + ty * 8;
    const int col = blockIdx.x * 64 + tx * 4;
    float4 bi = make_float4(0.f, 0.f, 0.f, 0.f);
    if (bias) bi = *(const float4*)(bias + col);
    #pragma unroll
    for (int i = 0; i < 8; i++) {
        float4 v;
        v.x = __fadd_rn(acc[i][0], bi.x); v.y = __fadd_rn(acc[i][1], bi.y);
        v.z = __fadd_rn(acc[i][2], bi.z); v.w = __fadd_rn(acc[i][3], bi.w);
        float* cp = C + (size_t)(row + i) * ldc + col;
        if (MODE == 1) {
            float4 r = *(const float4*)(Res + (size_t)(row + i) * ldc + col);
            v.x = __fadd_rn(v.x, r.x); v.y = __fadd_rn(v.y, r.y);
            v.z = __fadd_rn(v.z, r.z); v.w = __fadd_rn(v.w, r.w);
        }
        *(float4*)cp = v;
    }
}

// ---- merged QKV GEMM: blockIdx.z selects (W, b, C) --------------------------------
__launch_bounds__(256)
__global__ void gemm_qkv(const float* __restrict__ A,
                         const float* __restrict__ W0, const float* __restrict__ W1,
                         const float* __restrict__ W2,
                         const float* __restrict__ b0, const float* __restrict__ b1,
                         const float* __restrict__ b2,
                         float* __restrict__ C0, float* __restrict__ C1,
                         float* __restrict__ C2)
{
    const int z = blockIdx.z;
    const float* B    = (z == 0) ? W0 : (z == 1) ? W1 : W2;
    const float* bias = (z == 0) ? b0 : (z == 1) ? b1 : b2;
    float* C          = (z == 0) ? C0 : (z == 1) ? C1 : C2;

    __shared__ float As[16][128];
    __shared__ float Bs[16][64];
    const int tid = threadIdx.x;
    const int ty = tid >> 4, tx = tid & 15;
    const int ar = tid >> 1, ac = (tid & 1) * 8;
    const int br = tid >> 4, bc = (tid & 15) * 4;
    const float* Ap = A + (size_t)(blockIdx.y * 128 + ar) * CC + ac;
    const float* Bp = B + (size_t)br * CC + blockIdx.x * 64 + bc;
    float acc[8][4];
    #pragma unroll
    for (int i = 0; i < 8; i++)
        #pragma unroll
        for (int j = 0; j < 4; j++) acc[i][j] = 0.f;

    float4 nb0 = *(const float4*)Bp;   // weight prefetch (independent)
    GDC_WAIT();

    #pragma unroll 1
    for (int k0 = 0; k0 < CC; k0 += 16) {
        float4 a0 = *(const float4*)(Ap + k0);
        float4 a1 = *(const float4*)(Ap + k0 + 4);
        float4 b0v = (k0 == 0) ? nb0 : *(const float4*)(Bp + (size_t)k0 * CC);
        __syncthreads();
        As[ac + 0][ar] = a0.x; As[ac + 1][ar] = a0.y;
        As[ac + 2][ar] = a0.z; As[ac + 3][ar] = a0.w;
        As[ac + 4][ar] = a1.x; As[ac + 5][ar] = a1.y;
        As[ac + 6][ar] = a1.z; As[ac + 7][ar] = a1.w;
        *(float4*)&Bs[br][bc] = b0v;
        __syncthreads();
        #pragma unroll
        for (int k = 0; k < 16; k++) {
            float4 fa0 = *(const float4*)&As[k][ty * 8];
            float4 fa1 = *(const float4*)&As[k][ty * 8 + 4];
            float4 fb  = *(const float4*)&Bs[k][tx * 4];
            float av[8] = {fa0.x, fa0.y, fa0.z, fa0.w, fa1.x, fa1.y, fa1.z, fa1.w};
            float bv[4] = {fb.x, fb.y, fb.z, fb.w};
            #pragma unroll
            for (int i = 0; i < 8; i++)
                #pragma unroll
                for (int j = 0; j < 4; j++)
                    acc[i][j] = fmaf(av[i], bv[j], acc[i][j]);
        }
    }
    const int row = blockIdx.y * 128 + ty * 8;
    const int col = blockIdx.x * 64 + tx * 4;
    float4 bi = *(const float4*)(bias + col);
    #pragma unroll
    for (int i = 0; i < 8; i++) {
        float4 v;
        v.x = __fadd_rn(acc[i][0], bi.x); v.y = __fadd_rn(acc[i][1], bi.y);
        v.z = __fadd_rn(acc[i][2], bi.z); v.w = __fadd_rn(acc[i][3], bi.w);
        *(float4*)(C + (size_t)(row + i) * CC + col) = v;
    }
}

// ---- fused FF dual-GEMM: g = (A@Wa+ba) * relu(A@Wb+bb) ---------------------------
__launch_bounds__(256)
__global__ void gemm_ff(const float* __restrict__ A,
                        const float* __restrict__ Ba, const float* __restrict__ Bb,
                        float* __restrict__ C,
                        const float* __restrict__ ba, const float* __restrict__ bb)
{
    __shared__ float As[16][128];
    __shared__ float Bsa[16][64];
    __shared__ float Bsb[16][64];
    const int tid = threadIdx.x;
    const int ty = tid >> 4, tx = tid & 15;
    const int ar = tid >> 1, ac = (tid & 1) * 8;
    const int br = tid >> 4, bc = (tid & 15) * 4;
    const float* Ap  = A + (size_t)(blockIdx.y * 128 + ar) * CC + ac;
    const float* Bpa = Ba + (size_t)br * FFD + blockIdx.x * 64 + bc;
    const float* Bpb = Bb + (size_t)br * FFD + blockIdx.x * 64 + bc;
    float accA[8][4], accB[8][4];
    #pragma unroll
    for (int i = 0; i < 8; i++)
        #pragma unroll
        for (int j = 0; j < 4; j++) { accA[i][j] = 0.f; accB[i][j] = 0.f; }

    float4 np0 = *(const float4*)Bpa;  // weight prefetch (independent)
    float4 nq0 = *(const float4*)Bpb;
    GDC_WAIT();

    #pragma unroll 1
    for (int k0 = 0; k0 < CC; k0 += 16) {
        float4 a0 = *(const float4*)(Ap + k0);
        float4 a1 = *(const float4*)(Ap + k0 + 4);
        float4 p0 = (k0 == 0) ? np0 : *(const float4*)(Bpa + (size_t)k0 * FFD);
        float4 q0 = (k0 == 0) ? nq0 : *(const float4*)(Bpb + (size_t)k0 * FFD);
        __syncthreads();
        As[ac + 0][ar] = a0.x; As[ac + 1][ar] = a0.y;
        As[ac + 2][ar] = a0.z; As[ac + 3][ar] = a0.w;
        As[ac + 4][ar] = a1.x; As[ac + 5][ar] = a1.y;
        As[ac + 6][ar] = a1.z; As[ac + 7][ar] = a1.w;
        *(float4*)&Bsa[br][bc] = p0;
        *(float4*)&Bsb[br][bc] = q0;
        __syncthreads();
        #pragma unroll
        for (int k = 0; k < 16; k++) {
            float4 fa0 = *(const float4*)&As[k][ty * 8];
            float4 fa1 = *(const float4*)&As[k][ty * 8 + 4];
            float4 fp  = *(const float4*)&Bsa[k][tx * 4];
            float4 fq  = *(const float4*)&Bsb[k][tx * 4];
            float av[8] = {fa0.x, fa0.y, fa0.z, fa0.w, fa1.x, fa1.y, fa1.z, fa1.w};
            float pv[4] = {fp.x, fp.y, fp.z, fp.w};
            float qv[4] = {fq.x, fq.y, fq.z, fq.w};
            #pragma unroll
            for (int ii = 0; ii < 8; ii++)
                #pragma unroll
                for (int j = 0; j < 4; j++) {
                    accA[ii][j] = fmaf(av[ii], pv[j], accA[ii][j]);
                    accB[ii][j] = fmaf(av[ii], qv[j], accB[ii][j]);
                }
        }
    }
    const int row = blockIdx.y * 128 + ty * 8;
    const int col = blockIdx.x * 64 + tx * 4;
    float4 ba4 = *(const float4*)(ba + col);
    float4 bb4 = *(const float4*)(bb + col);
    float bav[4] = {ba4.x, ba4.y, ba4.z, ba4.w};
    float bbv[4] = {bb4.x, bb4.y, bb4.z, bb4.w};
    #pragma unroll
    for (int i = 0; i < 8; i++) {
        float o[4];
        #pragma unroll
        for (int j = 0; j < 4; j++) {
            float at = __fadd_rn(accA[i][j], bav[j]);
            float bt = __fadd_rn(accB[i][j], bbv[j]);
            o[j] = __fmul_rn(at, fmaxf(bt, 0.f));
        }
        *(float4*)(C + (size_t)(row + i) * FFD + col) = make_float4(o[0], o[1], o[2], o[3]);
    }
}

// ---- encoder stage 2: proj[b,o,p] = chain(S[o,p]; fmaf(encW[o,256+k], te[b,k])) + encB[o]
// Exact continuation of the ascending-512 chain split at k=256 (bitwise identical).
__launch_bounds__(256)
__global__ void enc2_k(const float* __restrict__ encW, const float* __restrict__ encB,
                       const float* __restrict__ S, float* __restrict__ proj)
{
    const int o = blockIdx.y;
    const int b = blockIdx.z;
    const int tid = threadIdx.x;
    const int p = blockIdx.x * 2048 + tid * 8;
    __shared__ float ws[256], ts[256];
    ws[tid] = encW[(size_t)o * 512 + 256 + tid];   // pure input: safe pre-wait
    GDC_WAIT();
    ts[tid] = g_te[b * 256 + tid];
    __syncthreads();
    float4 s0 = *(const float4*)(S + (size_t)o * NN + p);
    float4 s1 = *(const float4*)(S + (size_t)o * NN + p + 4);
    float a[8] = {s0.x, s0.y, s0.z, s0.w, s1.x, s1.y, s1.z, s1.w};
    #pragma unroll 8
    for (int k = 0; k < 256; k++) {
        float w = ws[k], t = ts[k];
        #pragma unroll
        for (int j = 0; j < 8; j++) a[j] = fmaf(w, t, a[j]);
    }
    float bb = encB[o];
    #pragma unroll
    for (int j = 0; j < 8; j++) a[j] = __fadd_rn(a[j], bb);
    float* op = proj + ((size_t)b * 512 + o) * NN + p;
    *(float4*)op       = make_float4(a[0], a[1], a[2], a[3]);
    *(float4*)(op + 4) = make_float4(a[4], a[5], a[6], a[7]);
}

// ---- LayerNorm: strictly sequential in-order reductions --------------------------
__launch_bounds__(256)
__global__ void ln_k(const float* __restrict__ x, float* __restrict__ y,
                     const float* __restrict__ s, const float* __restrict__ b)
{
    __shared__ float tile[32][257];
    __shared__ float sm[32], sd[32];
    const int t0 = blockIdx.x * 32;
    const int tid = threadIdx.x;
    GDC_WAIT();
    for (int i = tid; i < 32 * 256; i += 256) {
        int r = i >> 8, c = i & 255;
        tile[r][c] = x[(size_t)(t0 + r) * CC + c];
    }
    __syncthreads();
    if (tid < 32) {
        float sum = 0.f;
        for (int i = 0; i < 256; i++) sum = __fadd_rn(sum, tile[tid][i]);
        float mean = __fdiv_rn(sum, 256.f);
        float vs = 0.f;
        for (int i = 0; i < 256; i++) {
            float d = __fsub_rn(tile[tid][i], mean);
            vs = __fadd_rn(vs, __fmul_rn(d, d));
        }
        float var = __fdiv_rn(vs, 255.f);
        sm[tid] = mean;
        sd[tid] = sqrtf(__fadd_rn(var, 1e-6f));
    }
    __syncthreads();
    for (int i = tid; i < 32 * 256; i += 256) {
        int r = i >> 8, c = i & 255;
        float t2 = __fdiv_rn(__fsub_rn(tile[r][c], sm[r]), sd[r]);
        y[(size_t)(t0 + r) * CC + c] = __fadd_rn(__fmul_rn(t2, s[c]), b[c]);
    }
}

// ---- LSH hash (R cached in smem BEFORE wait; R is an input, independent) ----------
__global__ void hash_k(const float* __restrict__ Rl)
{
    __shared__ float Rs[1024];
    const int hb = ((blockIdx.x * 8) >> 12) & 7;     // uniform across block
    for (int i = threadIdx.x; i < 1024; i += 256) Rs[i] = Rl[hb * 1024 + i];
    __syncthreads();
    GDC_WAIT();
    int w = blockIdx.x * 8 + (threadIdx.x >> 5);
    int lane = threadIdx.x & 31;
    int n  = w & (NN - 1);
    int b  = w >> 15;
    float kv = g_kk[((size_t)(b * NN + n)) * CC + hb * HDIM + lane];
    float acc = 0.f;
    #pragma unroll
    for (int d = 0; d < 32; d++)
        acc = fmaf(__shfl_sync(0xffffffffu, kv, d), Rs[d * 32 + lane], acc);
    float val = acc; int idx = lane;
    float nacc = -acc;
    if (nacc > acc) { val = nacc; idx = lane + 32; }
    #pragma unroll
    for (int o = 16; o; o >>= 1) {
        float ov = __shfl_xor_sync(0xffffffffu, val, o);
        int   oi = __shfl_xor_sync(0xffffffffu, idx, o);
        if (ov > val || (ov == val && oi < idx)) { val = ov; idx = oi; }
    }
    if (lane == 0) g_codes[w] = idx;
}

// ---- stable counting sort per (b,h) ----------------------------------------------
__global__ void sort_k()
{
    const int bh = blockIdx.x;
    const int t = threadIdx.x;
    GDC_WAIT();
    const int* cp = g_codes + (size_t)bh * NN;
    int* op = g_order + (size_t)bh * NN;
    __shared__ int lh[64 * 65];
    __shared__ int bstart[64];
    __shared__ int tot[64];
    for (int i = 0; i < 64; i++) lh[t * 65 + i] = 0;
    const int base = t * 64;
    for (int i = 0; i < 64; i++) { int c = cp[base + i]; lh[t * 65 + c]++; }
    __syncthreads();
    int run = 0;
    for (int r = 0; r < 64; r++) { int x = lh[r * 65 + t]; lh[r * 65 + t] = run; run += x; }
    tot[t] = run;
    __syncthreads();
    if (t == 0) { int s = 0; for (int i = 0; i < 64; i++) { bstart[i] = s; s += tot[i]; } }
    __syncthreads();
    int cnt[64];
    for (int i = 0; i < 64; i++) cnt[i] = 0;
    for (int i = 0; i < 64; i++) {
        int c = cp[base + i];
        int pos = bstart[c] + lh[t * 65 + c] + cnt[c]++;
        op[pos] = base + i;
    }
}

// ---- chunk attention: expf, sequential sum, normalize-then-AV ---------------------
__launch_bounds__(256)
__global__ void attn_k()
{
    const int m = blockIdx.x, hh = blockIdx.y, b = blockIdx.z;
    __shared__ float qs[64][33], ks[64][33], vs[64][33];
    __shared__ float P[64][65];
    __shared__ float rsum[64];
    __shared__ int sidx[64];
    const int tid = threadIdx.x;
    GDC_WAIT();
    if (tid < 64) sidx[tid] = g_order[((size_t)(b * HH + hh)) * NN + m * 64 + tid];
    __syncthreads();
    const int row = tid >> 2, g = tid & 3;
    {
        int n0 = sidx[row];
        size_t off = ((size_t)(b * NN + n0)) * CC + hh * HDIM + g * 8;
        #pragma unroll
        for (int j = 0; j < 8; j++) {
            qs[row][g * 8 + j] = g_q[off + j];
            ks[row][g * 8 + j] = g_kk[off + j];
            vs[row][g * 8 + j] = g_v[off + j];
        }
    }
    __syncthreads();
    const float SQHD = 5.656854249492381f;  // sqrtf(32)
    float sc[16];
    float mx = -INFINITY;
    #pragma unroll
    for (int jj = 0; jj < 16; jj++) {
        int colI = g * 16 + jj;
        float sacc = 0.f;
        #pragma unroll
        for (int d = 0; d < 32; d++) sacc = fmaf(qs[row][d], ks[colI][d], sacc);
        sacc = __fdiv_rn(sacc, SQHD);
        sc[jj] = sacc;
        mx = fmaxf(mx, sacc);
    }
    mx = fmaxf(mx, __shfl_xor_sync(0xffffffffu, mx, 1));
    mx = fmaxf(mx, __shfl_xor_sync(0xffffffffu, mx, 2));
    #pragma unroll
    for (int jj = 0; jj < 16; jj++)
        P[row][g * 16 + jj] = expf(__fsub_rn(sc[jj], mx));   // fp32 pipe (≤2 ulp)
    __syncthreads();
    if (tid < 64) {
        float ssum = 0.f;
        for (int i = 0; i < 64; i++) ssum = __fadd_rn(ssum, P[tid][i]);
        rsum[tid] = ssum;
    }
    __syncthreads();
    float pn[16];
    #pragma unroll
    for (int jj = 0; jj < 16; jj++)
        pn[jj] = __fdiv_rn(P[row][g * 16 + jj], rsum[row]);
    __syncthreads();
    #pragma unroll
    for (int jj = 0; jj < 16; jj++) P[row][g * 16 + jj] = pn[jj];
    __syncthreads();
    float acc[8] = {0.f, 0.f, 0.f, 0.f, 0.f, 0.f, 0.f, 0.f};
    const int dg = g * 8;
    #pragma unroll 4
    for (int kk = 0; kk < 64; kk++) {
        float p = P[row][kk];
        #pragma unroll
        for (int j = 0; j < 8; j++) acc[j] = fmaf(p, vs[kk][dg + j], acc[j]);
    }
    int n0 = sidx[row];
    float* op = g_o + ((size_t)(b * NN + n0)) * CC + hh * HDIM + dg;
    #pragma unroll
    for (int j = 0; j < 8; j++) op[j] = acc[j];
}

// ---- encodings: double-precision transcendentals (feed the hash path; keep CR) ----
__global__ void pe_k()
{
    int idx = blockIdx.x * 256 + threadIdx.x;
    int c = idx >> 12, p = idx & 4095;
    int yy = p >> 6, xx = p & 63;
    const float L = (float)log(10000.0);
    float cf, pos; int is_sin;
    if (c < 64)       { cf = (float)c;         pos = (float)yy; is_sin = 1; }
    else if (c < 128) { cf = (float)(c - 64);  pos = (float)yy; is_sin = 0; }
    else if (c < 192) { cf = (float)(c - 128); pos = (float)xx; is_sin = 1; }
    else              { cf = (float)(c - 192); pos = (float)xx; is_sin = 0; }
    float t3 = __fdiv_rn(__fmul_rn(-L, cf), 64.f);
    float f  = (float)exp((double)t3);
    float a  = __fmul_rn(pos, f);
    g_pe[idx] = is_sin ? (float)sin((double)a) : (float)cos((double)a);
}

__global__ void te_k(const float* __restrict__ t)
{
    int idx = blockIdx.x * 256 + threadIdx.x;
    int b = idx >> 8, c = idx & 255;
    const float L = (float)log(10000.0);
    float cf = (float)(c < 128 ? c : c - 128);
    float t3 = __fdiv_rn(__fmul_rn(-L, cf), 128.f);
    float f  = (float)exp((double)t3);
    float a  = __fmul_rn(t[b], f);
    g_te[idx] = (c < 128) ? (float)sin((double)a) : (float)cos((double)a);
}

// h[b,p,c] = x[b,c,p]*proj[b,c,p] + proj[b,c+256,p]
__global__ void encode_k(const float* __restrict__ x, const float* __restrict__ proj)
{
    const int b = blockIdx.z;
    const int p0 = blockIdx.x * 32, c0 = blockIdx.y * 32;
    __shared__ float sx[32][33], sm[32][33], sb[32][33];
    const int tx = threadIdx.x, ty = threadIdx.y;
    GDC_WAIT();
    #pragma unroll
    for (int i = 0; i < 4; i++) {
        int c = c0 + ty + 8 * i;
        int p = p0 + tx;
        sx[ty + 8 * i][tx] = x[((size_t)b * CC + c) * NN + p];
        sm[ty + 8 * i][tx] = proj[((size_t)b * 512 + c) * NN + p];
        sb[ty + 8 * i][tx] = proj[((size_t)b * 512 + c + 256) * NN + p];
    }
    __syncthreads();
    #pragma unroll
    for (int i = 0; i < 4; i++) {
        int p = p0 + ty + 8 * i;
        int c = c0 + tx;
        float prod = __fmul_rn(sx[tx][ty + 8 * i], sm[tx][ty + 8 * i]);
        g_h[((size_t)b * NN + p) * CC + c] = __fadd_rn(prod, sb[tx][ty + 8 * i]);
    }
}

__global__ void out_k(float* __restrict__ out)
{
    const int b = blockIdx.z;
    const int p0 = blockIdx.x * 32, c0 = blockIdx.y * 32;
    __shared__ float s[32][33];
    const int tx = threadIdx.x, ty = threadIdx.y;
    GDC_WAIT();
    #pragma unroll
    for (int i = 0; i < 4; i++)
        s[ty + 8 * i][tx] = g_h[((size_t)b * NN + p0 + ty + 8 * i) * CC + c0 + tx];
    __syncthreads();
    #pragma unroll
    for (int i = 0; i < 4; i++)
        out[((size_t)b * CC + c0 + ty + 8 * i) * NN + p0 + tx] = s[tx][ty + 8 * i];
}

// ---- PDL launch helper ------------------------------------------------------------
template<typename F, typename... Args>
static inline void launch_pdl(F f, dim3 grid, dim3 block, Args... args)
{
    cudaLaunchConfig_t cfg = {};
    cfg.gridDim = grid;
    cfg.blockDim = block;
    cudaLaunchAttribute attr[1];
    attr[0].id = cudaLaunchAttributeProgrammaticStreamSerialization;
    attr[0].val.programmaticStreamSerializationAllowed = 1;
    cfg.attrs = attr;
    cfg.numAttrs = 1;
    if (cudaLaunchKernelEx(&cfg, f, args...) != cudaSuccess) {
        cfg.attrs = nullptr;
        cfg.numAttrs = 0;
        cudaLaunchKernelEx(&cfg, f, args...);
    }
}

extern "C" void kernel_launch(void* const* d_in, const int* in_sizes, int n_in,
                              void* d_out, int out_size)
{
    (void)in_sizes; (void)n_in; (void)out_size;
    const float* x    = (const float*)d_in[0];
    const float* tt   = (const float*)d_in[1];
    const float* encW = (const float*)d_in[3];
    const float* encB = (const float*)d_in[4];
    const float* ln1s = (const float*)d_in[5];
    const float* ln1b = (const float*)d_in[6];
    const float* Wq   = (const float*)d_in[7];
    const float* bq   = (const float*)d_in[8];
    const float* Wk   = (const float*)d_in[9];
    const float* bk   = (const float*)d_in[10];
    const float* Wv   = (const float*)d_in[11];
    const float* bv   = (const float*)d_in[12];
    const float* Wo   = (const float*)d_in[13];
    const float* bo   = (const float*)d_in[14];
    const float* R    = (const float*)d_in[15];
    const float* ln2s = (const float*)d_in[16];
    const float* ln2b = (const float*)d_in[17];
    const float* Wa   = (const float*)d_in[18];
    const float* ba   = (const float*)d_in[19];
    const float* Wb   = (const float*)d_in[20];
    const float* bb   = (const float*)d_in[21];
    const float* Wc   = (const float*)d_in[22];
    const float* bc   = (const float*)d_in[23];
    float* out = (float*)d_out;

    float *ph, *pu, *pq, *pk, *pv, *po, *pg, *ppe;
    cudaGetSymbolAddress((void**)&ph, g_h);
    cudaGetSymbolAddress((void**)&pu, g_u);
    cudaGetSymbolAddress((void**)&pq, g_q);
    cudaGetSymbolAddress((void**)&pk, g_kk);
    cudaGetSymbolAddress((void**)&pv, g_v);
    cudaGetSymbolAddress((void**)&po, g_o);
    cudaGetSymbolAddress((void**)&pg, g_g);
    cudaGetSymbolAddress((void**)&ppe, g_pe);

    pe_k<<<4096, 256>>>();
    te_k<<<8, 256>>>(tt);
    // S = encW[:, :256] @ pe  (batch-independent first half of the encoder chain)
    // plain launch: B operand (pe) is device-written, so the pre-wait prefetch
    // inside gemm_k must not overlap pe_k.
    gemm_k<0><<<dim3(64, 4), 256>>>(encW, 512, ppe, NN, pu, NN,
                                    (const float*)nullptr, (const float*)nullptr, 256);
    launch_pdl(enc2_k, dim3(2, 512, BB), dim3(256), encW, encB, (const float*)pu, pg);
    launch_pdl(encode_k, dim3(128, 8, BB), dim3(32, 8), x, pg);

    for (int l = 0; l < LL; l++) {
        launch_pdl(ln_k, dim3(BNT / 32), dim3(256), (const float*)ph, pu,
                   ln1s + l * CC, ln1b + l * CC);
        launch_pdl(gemm_qkv, dim3(4, 256, 3), dim3(256), (const float*)pu,
                   Wq + (size_t)l * CC * CC, Wk + (size_t)l * CC * CC, Wv + (size_t)l * CC * CC,
                   bq + l * CC, bk + l * CC, bv + l * CC, pq, pk, pv);
        launch_pdl(hash_k, dim3(32768), dim3(256), R + (size_t)l * HH * HDIM * 32);
        launch_pdl(sort_k, dim3(64), dim3(64));
        launch_pdl(attn_k, dim3(64, HH, BB), dim3(256));
        launch_pdl(gemm_k<1>, dim3(4, 256), dim3(256), (const float*)po, (int)CC,
                   Wo + (size_t)l * CC * CC, (int)CC, ph, (int)CC,
                   bo + l * CC, (const float*)ph, (int)CC);
        launch_pdl(ln_k, dim3(BNT / 32), dim3(256), (const float*)ph, pu,
                   ln2s + l * CC, ln2b + l * CC);
        launch_pdl(gemm_ff, dim3(12, 256), dim3(256), (const float*)pu,
                   Wa + (size_t)l * CC * FFD, Wb + (size_t)l * CC * FFD, pg,
                   ba + l * FFD, bb + l * FFD);
        launch_pdl(gemm_k<1>, dim3(4, 256), dim3(256), (const float*)pg, (int)FFD,
                   Wc + (size_t)l * FFD * CC, (int)CC, ph, (int)CC,
                   bc + l * CC, (const float*)ph, (int)FFD);
    }

    launch_pdl(out_k, dim3(128, 8, BB), dim3(32, 8), out);
}